// round 3
// baseline (speedup 1.0000x reference)
#include <cuda_runtime.h>
#include <math.h>

// Problem constants
#define BB   4
#define SS   2048
#define HH   2048
#define NHH  16
#define NKV  4
#define HD   128
#define MTOK (BB*SS)          // 8192 tokens
#define NQKV 3072             // (16 + 2*4) * 128
#define QOFF 0
#define KOFF 2048
#define VOFF 2560

// Scratch (declared as device globals; allocation rules forbid cudaMalloc)
__device__ float g_qkv[(size_t)MTOK * NQKV];   // ~100.7 MB
__device__ float g_attn[(size_t)MTOK * HH];    // 64 MB

// ---------------------------------------------------------------------------
// GEMM: C[M,N] = A[M,K] * B[K,N] + bias[N]
// BM=128, BN=128, BK=16, 256 threads, 8x8 per-thread microtile,
// double-buffered smem, float4 global loads.
// M % 128 == 0, N % 128 == 0, K % 16 == 0 (true for all our shapes).
// ---------------------------------------------------------------------------
__global__ __launch_bounds__(256)
void gemm_bias_kernel(const float* __restrict__ A,
                      const float* __restrict__ Bw,
                      const float* __restrict__ bias,
                      float* __restrict__ C,
                      int M, int N, int K)
{
    __shared__ float As[2][128][17];   // [m][k], padded k-stride (bank-safe reads)
    __shared__ float Bs[2][16][128];   // [k][n]

    const int tid = threadIdx.x;
    const int tx  = tid & 15;          // 0..15 (column group)
    const int ty  = tid >> 4;          // 0..15 (row group)
    const int m0  = blockIdx.y * 128;
    const int n0  = blockIdx.x * 128;

    // global->smem load mapping
    const int arow = tid >> 2;           // 0..63 (and +64)
    const int acol = (tid & 3) * 4;      // 0,4,8,12
    const int brow = tid >> 5;           // 0..7 (and +8)
    const int bcol = (tid & 31) * 4;     // 0..124

    float acc[8][8];
#pragma unroll
    for (int i = 0; i < 8; i++)
#pragma unroll
        for (int j = 0; j < 8; j++) acc[i][j] = 0.0f;

    float4 ra0, ra1, rb0, rb1;

    // prologue: load tile 0
    {
        const int k0 = 0;
        ra0 = *(const float4*)(A + (size_t)(m0 + arow)      * K + k0 + acol);
        ra1 = *(const float4*)(A + (size_t)(m0 + arow + 64) * K + k0 + acol);
        rb0 = *(const float4*)(Bw + (size_t)(k0 + brow)     * N + n0 + bcol);
        rb1 = *(const float4*)(Bw + (size_t)(k0 + brow + 8) * N + n0 + bcol);
    }
    {
        As[0][arow][acol + 0] = ra0.x; As[0][arow][acol + 1] = ra0.y;
        As[0][arow][acol + 2] = ra0.z; As[0][arow][acol + 3] = ra0.w;
        As[0][arow + 64][acol + 0] = ra1.x; As[0][arow + 64][acol + 1] = ra1.y;
        As[0][arow + 64][acol + 2] = ra1.z; As[0][arow + 64][acol + 3] = ra1.w;
        *(float4*)&Bs[0][brow][bcol]     = rb0;
        *(float4*)&Bs[0][brow + 8][bcol] = rb1;
    }
    __syncthreads();

    const int nk = K >> 4;
    for (int t = 0; t < nk; ++t) {
        const int cur = t & 1;
        const int nxt = cur ^ 1;

        if (t + 1 < nk) {   // issue next-tile global loads early
            const int k0 = (t + 1) << 4;
            ra0 = *(const float4*)(A + (size_t)(m0 + arow)      * K + k0 + acol);
            ra1 = *(const float4*)(A + (size_t)(m0 + arow + 64) * K + k0 + acol);
            rb0 = *(const float4*)(Bw + (size_t)(k0 + brow)     * N + n0 + bcol);
            rb1 = *(const float4*)(Bw + (size_t)(k0 + brow + 8) * N + n0 + bcol);
        }

#pragma unroll
        for (int k = 0; k < 16; ++k) {
            float a[8];
#pragma unroll
            for (int i = 0; i < 4; i++) {
                a[i]     = As[cur][ty * 4 + i][k];
                a[i + 4] = As[cur][64 + ty * 4 + i][k];
            }
            float4 b0 = *(const float4*)&Bs[cur][k][tx * 4];
            float4 b1 = *(const float4*)&Bs[cur][k][64 + tx * 4];
            float bb[8] = {b0.x, b0.y, b0.z, b0.w, b1.x, b1.y, b1.z, b1.w};
#pragma unroll
            for (int i = 0; i < 8; i++)
#pragma unroll
                for (int j = 0; j < 8; j++)
                    acc[i][j] += a[i] * bb[j];
        }

        if (t + 1 < nk) {
            As[nxt][arow][acol + 0] = ra0.x; As[nxt][arow][acol + 1] = ra0.y;
            As[nxt][arow][acol + 2] = ra0.z; As[nxt][arow][acol + 3] = ra0.w;
            As[nxt][arow + 64][acol + 0] = ra1.x; As[nxt][arow + 64][acol + 1] = ra1.y;
            As[nxt][arow + 64][acol + 2] = ra1.z; As[nxt][arow + 64][acol + 3] = ra1.w;
            *(float4*)&Bs[nxt][brow][bcol]     = rb0;
            *(float4*)&Bs[nxt][brow + 8][bcol] = rb1;
        }
        __syncthreads();
    }

    // epilogue with bias
    float4 biasA = *(const float4*)(bias + n0 + tx * 4);
    float4 biasB = *(const float4*)(bias + n0 + 64 + tx * 4);
#pragma unroll
    for (int i = 0; i < 8; i++) {
        const int row = m0 + ((i < 4) ? (ty * 4 + i) : (64 + ty * 4 + (i - 4)));
        float4 va = make_float4(acc[i][0] + biasA.x, acc[i][1] + biasA.y,
                                acc[i][2] + biasA.z, acc[i][3] + biasA.w);
        float4 vb = make_float4(acc[i][4] + biasB.x, acc[i][5] + biasB.y,
                                acc[i][6] + biasB.z, acc[i][7] + biasB.w);
        *(float4*)(C + (size_t)row * N + n0 + tx * 4)      = va;
        *(float4*)(C + (size_t)row * N + n0 + 64 + tx * 4) = vb;
    }
}

// ---------------------------------------------------------------------------
// RoPE (full rotation, ROT == HD == 128) applied in-place to Q and K heads
// of g_qkv. One thread per (token, head, pair j) with j in [0,64).
// out[j]    = x[j]   * cos[j]    - x[j+64] * sin[j]
// out[j+64] = x[j+64]* cos[j+64] + x[j]    * sin[j+64]
// ---------------------------------------------------------------------------
__global__ __launch_bounds__(256)
void rope_kernel(float* __restrict__ qkv,
                 const float* __restrict__ cosp,
                 const float* __restrict__ sinp)
{
    const int total = MTOK * (NHH + NKV) * 64;   // 8192 * 20 * 64
    int idx = blockIdx.x * blockDim.x + threadIdx.x;
    if (idx >= total) return;
    const int t    = idx / ((NHH + NKV) * 64);
    const int rem  = idx - t * ((NHH + NKV) * 64);
    const int head = rem >> 6;
    const int j    = rem & 63;
    const int base = (head < NHH) ? head * HD : KOFF + (head - NHH) * HD;

    float* p = qkv + (size_t)t * NQKV + base;
    const float x1 = p[j];
    const float x2 = p[j + 64];
    const float* cp = cosp + (size_t)t * 128;
    const float* sp = sinp + (size_t)t * 128;
    p[j]      = x1 * cp[j]      - x2 * sp[j];
    p[j + 64] = x2 * cp[j + 64] + x1 * sp[j + 64];
}

// ---------------------------------------------------------------------------
// Flash attention (non-causal, GQA 16q/4kv, HD=128).
// Grid: (S/64 q-blocks, NH heads, B). 256 threads = 16x16.
// Each CTA: 64 q rows, streams 32 tiles of 64 kv rows, online softmax.
// Dynamic smem: Q,K,V tiles 64x128 (stride 132) + P tile 64x64 (stride 68).
// ---------------------------------------------------------------------------
#define ATTN_SMEM_FLOATS (3 * 64 * 132 + 64 * 68)
#define ATTN_SMEM_BYTES  (ATTN_SMEM_FLOATS * 4)

__global__ __launch_bounds__(256)
void attn_kernel(const float* __restrict__ qkv, float* __restrict__ attn_out)
{
    extern __shared__ float smem[];
    float* Qs = smem;                    // [64][132]
    float* Ks = Qs + 64 * 132;           // [64][132]
    float* Vs = Ks + 64 * 132;           // [64][132]
    float* Ps = Vs + 64 * 132;           // [64][68]

    const int tid = threadIdx.x;
    const int tx  = tid & 15;            // column group (4 cols)
    const int ty  = tid >> 4;            // row group (4 rows)
    const int qb  = blockIdx.x;
    const int h   = blockIdx.y;
    const int b   = blockIdx.z;
    const int g   = h >> 2;              // kv head
    const int tq0 = b * SS + qb * 64;
    const float scale = 0.08838834764831845f;   // 128^-0.5

    const int lrow = tid >> 5;           // 0..7
    const int lcol = (tid & 31) * 4;     // 0..124

    // Load Q tile once, pre-scaled by 1/sqrt(HD)
    {
        const int cb = h * HD;
#pragma unroll
        for (int r = lrow; r < 64; r += 8) {
            float4 v = *(const float4*)(qkv + (size_t)(tq0 + r) * NQKV + cb + lcol);
            v.x *= scale; v.y *= scale; v.z *= scale; v.w *= scale;
            *(float4*)(Qs + r * 132 + lcol) = v;
        }
    }

    float m_i[4], l_i[4], O[4][8];
#pragma unroll
    for (int i = 0; i < 4; i++) {
        m_i[i] = -INFINITY;
        l_i[i] = 0.0f;
#pragma unroll
        for (int j = 0; j < 8; j++) O[i][j] = 0.0f;
    }

    for (int kt = 0; kt < SS / 64; ++kt) {
        const int tk0 = b * SS + kt * 64;
        // Load K and V tiles
#pragma unroll
        for (int r = lrow; r < 64; r += 8) {
            *(float4*)(Ks + r * 132 + lcol) =
                *(const float4*)(qkv + (size_t)(tk0 + r) * NQKV + KOFF + g * HD + lcol);
            *(float4*)(Vs + r * 132 + lcol) =
                *(const float4*)(qkv + (size_t)(tk0 + r) * NQKV + VOFF + g * HD + lcol);
        }
        __syncthreads();

        // S = Qs * Ks^T  (64x64), per-thread 4x4 fragment
        float s[4][4];
#pragma unroll
        for (int i = 0; i < 4; i++)
#pragma unroll
            for (int j = 0; j < 4; j++) s[i][j] = 0.0f;

#pragma unroll 8
        for (int kk = 0; kk < 128; kk += 4) {
            float4 q4[4], k4[4];
#pragma unroll
            for (int i = 0; i < 4; i++)
                q4[i] = *(const float4*)(Qs + (ty * 4 + i) * 132 + kk);
#pragma unroll
            for (int j = 0; j < 4; j++)
                k4[j] = *(const float4*)(Ks + (tx * 4 + j) * 132 + kk);
#pragma unroll
            for (int i = 0; i < 4; i++)
#pragma unroll
                for (int j = 0; j < 4; j++) {
                    s[i][j] += q4[i].x * k4[j].x;
                    s[i][j] += q4[i].y * k4[j].y;
                    s[i][j] += q4[i].z * k4[j].z;
                    s[i][j] += q4[i].w * k4[j].w;
                }
        }

        // Online softmax update (row reductions across tx = lane bits 0..3)
#pragma unroll
        for (int i = 0; i < 4; i++) {
            float rm = fmaxf(fmaxf(s[i][0], s[i][1]), fmaxf(s[i][2], s[i][3]));
#pragma unroll
            for (int mk = 8; mk >= 1; mk >>= 1)
                rm = fmaxf(rm, __shfl_xor_sync(0xffffffffu, rm, mk));
            const float mn = fmaxf(m_i[i], rm);
            const float alpha = __expf(m_i[i] - mn);
            float rs = 0.0f;
#pragma unroll
            for (int j = 0; j < 4; j++) {
                s[i][j] = __expf(s[i][j] - mn);
                rs += s[i][j];
            }
#pragma unroll
            for (int mk = 8; mk >= 1; mk >>= 1)
                rs += __shfl_xor_sync(0xffffffffu, rs, mk);
            l_i[i] = l_i[i] * alpha + rs;
            m_i[i] = mn;
#pragma unroll
            for (int j = 0; j < 8; j++) O[i][j] *= alpha;
            *(float4*)(Ps + (ty * 4 + i) * 68 + tx * 4) =
                make_float4(s[i][0], s[i][1], s[i][2], s[i][3]);
        }
        __syncthreads();

        // O += P * V  (64x64 @ 64x128), per-thread rows ty*4.., cols tx*4.. & 64+tx*4..
#pragma unroll 8
        for (int k = 0; k < 64; ++k) {
            float p0 = Ps[(ty * 4 + 0) * 68 + k];
            float p1 = Ps[(ty * 4 + 1) * 68 + k];
            float p2 = Ps[(ty * 4 + 2) * 68 + k];
            float p3 = Ps[(ty * 4 + 3) * 68 + k];
            float4 va = *(const float4*)(Vs + k * 132 + tx * 4);
            float4 vb = *(const float4*)(Vs + k * 132 + 64 + tx * 4);
            O[0][0] += p0 * va.x; O[0][1] += p0 * va.y; O[0][2] += p0 * va.z; O[0][3] += p0 * va.w;
            O[0][4] += p0 * vb.x; O[0][5] += p0 * vb.y; O[0][6] += p0 * vb.z; O[0][7] += p0 * vb.w;
            O[1][0] += p1 * va.x; O[1][1] += p1 * va.y; O[1][2] += p1 * va.z; O[1][3] += p1 * va.w;
            O[1][4] += p1 * vb.x; O[1][5] += p1 * vb.y; O[1][6] += p1 * vb.z; O[1][7] += p1 * vb.w;
            O[2][0] += p2 * va.x; O[2][1] += p2 * va.y; O[2][2] += p2 * va.z; O[2][3] += p2 * va.w;
            O[2][4] += p2 * vb.x; O[2][5] += p2 * vb.y; O[2][6] += p2 * vb.z; O[2][7] += p2 * vb.w;
            O[3][0] += p3 * va.x; O[3][1] += p3 * va.y; O[3][2] += p3 * va.z; O[3][3] += p3 * va.w;
            O[3][4] += p3 * vb.x; O[3][5] += p3 * vb.y; O[3][6] += p3 * vb.z; O[3][7] += p3 * vb.w;
        }
        __syncthreads();
    }

    // Normalize and write to attn_out[token][h*128 + d]
#pragma unroll
    for (int i = 0; i < 4; i++) {
        const float inv = 1.0f / l_i[i];
        const int row = tq0 + ty * 4 + i;
        float* dst = attn_out + (size_t)row * HH + h * HD;
        float4 oa = make_float4(O[i][0] * inv, O[i][1] * inv, O[i][2] * inv, O[i][3] * inv);
        float4 ob = make_float4(O[i][4] * inv, O[i][5] * inv, O[i][6] * inv, O[i][7] * inv);
        *(float4*)(dst + tx * 4)      = oa;
        *(float4*)(dst + 64 + tx * 4) = ob;
    }
}

// ---------------------------------------------------------------------------
// Launch
// ---------------------------------------------------------------------------
extern "C" void kernel_launch(void* const* d_in, const int* in_sizes, int n_in,
                              void* d_out, int out_size)
{
    (void)in_sizes; (void)n_in; (void)out_size;
    const float* hs    = (const float*)d_in[0];
    const float* cosp  = (const float*)d_in[1];
    const float* sinp  = (const float*)d_in[2];
    const float* w_qkv = (const float*)d_in[3];
    const float* b_qkv = (const float*)d_in[4];
    const float* w_o   = (const float*)d_in[5];
    const float* b_o   = (const float*)d_in[6];
    float* out = (float*)d_out;

    float *qkv, *attn;
    cudaGetSymbolAddress((void**)&qkv, g_qkv);
    cudaGetSymbolAddress((void**)&attn, g_attn);

    // 1) QKV projection + bias
    gemm_bias_kernel<<<dim3(NQKV / 128, MTOK / 128), 256>>>(
        hs, w_qkv, b_qkv, qkv, MTOK, NQKV, HH);

    // 2) RoPE on q and k heads (in-place)
    {
        const int total = MTOK * (NHH + NKV) * 64;
        rope_kernel<<<(total + 255) / 256, 256>>>(qkv, cosp, sinp);
    }

    // 3) Flash attention
    cudaFuncSetAttribute((const void*)attn_kernel,
                         cudaFuncAttributeMaxDynamicSharedMemorySize,
                         ATTN_SMEM_BYTES);
    attn_kernel<<<dim3(SS / 64, NHH, BB), 256, ATTN_SMEM_BYTES>>>(qkv, attn);

    // 4) Output projection + bias -> d_out
    gemm_bias_kernel<<<dim3(HH / 128, MTOK / 128), 256>>>(
        attn, w_o, b_o, out, MTOK, HH, HH);
}

// round 4
// speedup vs baseline: 1.3833x; 1.3833x over previous
#include <cuda_runtime.h>
#include <math.h>
#include <stdint.h>

// Problem constants
#define BB   4
#define SS   2048
#define HH   2048
#define NHH  16
#define NKV  4
#define HD   128
#define MTOK (BB*SS)          // 8192 tokens
#define NQKV 3072             // (16 + 2*4) * 128
#define QOFF 0
#define KOFF 2048
#define VOFF 2560

// Scratch (allocation rules forbid cudaMalloc)
__device__ float g_qkv[(size_t)MTOK * NQKV];   // ~100.7 MB
__device__ float g_attn[(size_t)MTOK * HH];    // 64 MB

// ---------------------------------------------------------------------------
// Helpers
// ---------------------------------------------------------------------------
__device__ __forceinline__ uint32_t f2tf32(float x) {
    uint32_t y;
    asm("cvt.rna.tf32.f32 %0, %1;" : "=r"(y) : "f"(x));
    return y;
}

__device__ __forceinline__ uint32_t smem_u32(const void* p) {
    return (uint32_t)__cvta_generic_to_shared(p);
}

__device__ __forceinline__ void ldmatrix_x4(uint32_t* d, uint32_t addr) {
    asm volatile("ldmatrix.sync.aligned.m8n8.x4.shared.b16 {%0,%1,%2,%3}, [%4];"
                 : "=r"(d[0]), "=r"(d[1]), "=r"(d[2]), "=r"(d[3])
                 : "r"(addr));
}

__device__ __forceinline__ void mma_tf32(float* c, const uint32_t* a, const uint32_t* b) {
    asm volatile(
        "mma.sync.aligned.m16n8k8.row.col.f32.tf32.tf32.f32 "
        "{%0,%1,%2,%3}, {%4,%5,%6,%7}, {%8,%9}, {%0,%1,%2,%3};"
        : "+f"(c[0]), "+f"(c[1]), "+f"(c[2]), "+f"(c[3])
        : "r"(a[0]), "r"(a[1]), "r"(a[2]), "r"(a[3]), "r"(b[0]), "r"(b[1]));
}

// ---------------------------------------------------------------------------
// TF32 tensor-core GEMM: C[M,N] = A[M,K]*B[K,N] + bias[N]
// CTA tile 128x128x32, 256 threads = 8 warps (4 m x 2 n), warp tile 32x64.
// Smem: A as [m][k] and B transposed as [n][k], both in 8x4-fp32 atoms with
// XOR swizzle (k4 ^= row&7) -> conflict-free STS.128 copy and ldmatrix loads.
// Inputs rounded to tf32 with cvt.rna (unbiased) during copy.
// Requires M%128==0, N%128==0, K%32==0.
// ---------------------------------------------------------------------------
__global__ __launch_bounds__(256)
void gemm_tf32_kernel(const float* __restrict__ A,
                      const float* __restrict__ Bw,
                      const float* __restrict__ bias,
                      float* __restrict__ C,
                      int M, int N, int K)
{
    __shared__ uint32_t As[128 * 32];   // [m][k] swizzled
    __shared__ uint32_t Bs[128 * 32];   // [n][k] swizzled (B transposed)

    const int tid  = threadIdx.x;
    const int lane = tid & 31;
    const int warp = tid >> 5;
    const int wm   = (warp >> 1) * 32;     // warp m-offset (0,32,64,96)
    const int wn   = (warp & 1) * 64;      // warp n-offset (0,64)
    const int m0   = blockIdx.y * 128;
    const int n0   = blockIdx.x * 128;

    const int q = lane >> 3;               // ldmatrix matrix index
    const int r = lane & 7;                // ldmatrix row index

    const uint32_t sA = smem_u32(As);
    const uint32_t sB = smem_u32(Bs);

    // ldmatrix row bases (row & 7 == r for all, since offsets are multiples of 8)
    const int rowA0 = wm + 8 * (q & 1) + r;     // + 16*mi
    const int rowB0 = wn + 8 * (q >> 1) + r;    // + 16*jp

    float acc[2][8][4];
#pragma unroll
    for (int i = 0; i < 2; i++)
#pragma unroll
        for (int j = 0; j < 8; j++)
#pragma unroll
            for (int v = 0; v < 4; v++) acc[i][j][v] = 0.0f;

    // Copy-index precompute
    // A: per it, idx = tid + 256*it : m = idx>>3 (0..127), k4 = idx&7
    // B: per it, idx                : n = idx&127,        k4 = idx>>7
    const int nk = K >> 5;

    float4 pa[4];
    float  pb[4][4];

    // ---- prologue: load tile 0 into registers ----
#pragma unroll
    for (int it = 0; it < 4; ++it) {
        const int idx = tid + 256 * it;
        const int am = idx >> 3, ak4 = idx & 7;
        pa[it] = *(const float4*)(A + (size_t)(m0 + am) * K + 4 * ak4);
        const int bn = idx & 127, bk4 = idx >> 7;
#pragma unroll
        for (int i = 0; i < 4; i++)
            pb[it][i] = Bw[(size_t)(4 * bk4 + i) * N + n0 + bn];
    }
    // store to smem (tf32 rounding)
#pragma unroll
    for (int it = 0; it < 4; ++it) {
        const int idx = tid + 256 * it;
        const int am = idx >> 3, ak4 = idx & 7;
        uint4 va = make_uint4(f2tf32(pa[it].x), f2tf32(pa[it].y),
                              f2tf32(pa[it].z), f2tf32(pa[it].w));
        *(uint4*)&As[am * 32 + 4 * (ak4 ^ (am & 7))] = va;
        const int bn = idx & 127, bk4 = idx >> 7;
        uint4 vb = make_uint4(f2tf32(pb[it][0]), f2tf32(pb[it][1]),
                              f2tf32(pb[it][2]), f2tf32(pb[it][3]));
        *(uint4*)&Bs[bn * 32 + 4 * (bk4 ^ (bn & 7))] = vb;
    }
    __syncthreads();

    for (int t = 0; t < nk; ++t) {
        // prefetch next tile into registers
        if (t + 1 < nk) {
            const int k0 = (t + 1) << 5;
#pragma unroll
            for (int it = 0; it < 4; ++it) {
                const int idx = tid + 256 * it;
                const int am = idx >> 3, ak4 = idx & 7;
                pa[it] = *(const float4*)(A + (size_t)(m0 + am) * K + k0 + 4 * ak4);
                const int bn = idx & 127, bk4 = idx >> 7;
#pragma unroll
                for (int i = 0; i < 4; i++)
                    pb[it][i] = Bw[(size_t)(k0 + 4 * bk4 + i) * N + n0 + bn];
            }
        }

        // compute on current smem tile: 4 k-steps of 8
#pragma unroll
        for (int s = 0; s < 4; ++s) {
            uint32_t af[2][4];
#pragma unroll
            for (int mi = 0; mi < 2; ++mi) {
                const int row = rowA0 + 16 * mi;
                const int k4  = (2 * s + (q >> 1)) ^ r;
                ldmatrix_x4(af[mi], sA + (uint32_t)((row * 32 + 4 * k4) << 2));
            }
            uint32_t bf[8][2];
#pragma unroll
            for (int jp = 0; jp < 4; ++jp) {
                const int row = rowB0 + 16 * jp;
                const int k4  = (2 * s + (q & 1)) ^ r;
                uint32_t tmp[4];
                ldmatrix_x4(tmp, sB + (uint32_t)((row * 32 + 4 * k4) << 2));
                bf[2 * jp][0]     = tmp[0];
                bf[2 * jp][1]     = tmp[1];
                bf[2 * jp + 1][0] = tmp[2];
                bf[2 * jp + 1][1] = tmp[3];
            }
#pragma unroll
            for (int mi = 0; mi < 2; ++mi)
#pragma unroll
                for (int nj = 0; nj < 8; ++nj)
                    mma_tf32(acc[mi][nj], af[mi], bf[nj]);
        }
        __syncthreads();

        if (t + 1 < nk) {
#pragma unroll
            for (int it = 0; it < 4; ++it) {
                const int idx = tid + 256 * it;
                const int am = idx >> 3, ak4 = idx & 7;
                uint4 va = make_uint4(f2tf32(pa[it].x), f2tf32(pa[it].y),
                                      f2tf32(pa[it].z), f2tf32(pa[it].w));
                *(uint4*)&As[am * 32 + 4 * (ak4 ^ (am & 7))] = va;
                const int bn = idx & 127, bk4 = idx >> 7;
                uint4 vb = make_uint4(f2tf32(pb[it][0]), f2tf32(pb[it][1]),
                                      f2tf32(pb[it][2]), f2tf32(pb[it][3]));
                *(uint4*)&Bs[bn * 32 + 4 * (bk4 ^ (bn & 7))] = vb;
            }
            __syncthreads();
        }
    }

    // epilogue: acc + bias -> C
    const int g   = lane >> 2;
    const int tig = lane & 3;
#pragma unroll
    for (int mi = 0; mi < 2; ++mi) {
#pragma unroll
        for (int nj = 0; nj < 8; ++nj) {
            const int row = m0 + wm + 16 * mi + g;
            const int col = n0 + wn + 8 * nj + 2 * tig;
            const float b0v = __ldg(bias + col);
            const float b1v = __ldg(bias + col + 1);
            float2 v0 = make_float2(acc[mi][nj][0] + b0v, acc[mi][nj][1] + b1v);
            float2 v1 = make_float2(acc[mi][nj][2] + b0v, acc[mi][nj][3] + b1v);
            *(float2*)(C + (size_t)row * N + col)       = v0;
            *(float2*)(C + (size_t)(row + 8) * N + col) = v1;
        }
    }
}

// ---------------------------------------------------------------------------
// RoPE (full rotation, ROT == HD == 128) applied in-place to Q and K heads.
// ---------------------------------------------------------------------------
__global__ __launch_bounds__(256)
void rope_kernel(float* __restrict__ qkv,
                 const float* __restrict__ cosp,
                 const float* __restrict__ sinp)
{
    const int total = MTOK * (NHH + NKV) * 64;
    int idx = blockIdx.x * blockDim.x + threadIdx.x;
    if (idx >= total) return;
    const int t    = idx / ((NHH + NKV) * 64);
    const int rem  = idx - t * ((NHH + NKV) * 64);
    const int head = rem >> 6;
    const int j    = rem & 63;
    const int base = (head < NHH) ? head * HD : KOFF + (head - NHH) * HD;

    float* p = qkv + (size_t)t * NQKV + base;
    const float x1 = p[j];
    const float x2 = p[j + 64];
    const float* cp = cosp + (size_t)t * 128;
    const float* sp = sinp + (size_t)t * 128;
    p[j]      = x1 * cp[j]      - x2 * sp[j];
    p[j + 64] = x2 * cp[j + 64] + x1 * sp[j + 64];
}

// ---------------------------------------------------------------------------
// Flash attention (non-causal, GQA 16q/4kv, HD=128) — SIMT fp32 (unchanged).
// ---------------------------------------------------------------------------
#define ATTN_SMEM_FLOATS (3 * 64 * 132 + 64 * 68)
#define ATTN_SMEM_BYTES  (ATTN_SMEM_FLOATS * 4)

__global__ __launch_bounds__(256)
void attn_kernel(const float* __restrict__ qkv, float* __restrict__ attn_out)
{
    extern __shared__ float smem[];
    float* Qs = smem;                    // [64][132]
    float* Ks = Qs + 64 * 132;           // [64][132]
    float* Vs = Ks + 64 * 132;           // [64][132]
    float* Ps = Vs + 64 * 132;           // [64][68]

    const int tid = threadIdx.x;
    const int tx  = tid & 15;
    const int ty  = tid >> 4;
    const int qb  = blockIdx.x;
    const int h   = blockIdx.y;
    const int b   = blockIdx.z;
    const int g   = h >> 2;
    const int tq0 = b * SS + qb * 64;
    const float scale = 0.08838834764831845f;

    const int lrow = tid >> 5;
    const int lcol = (tid & 31) * 4;

    {
        const int cb = h * HD;
#pragma unroll
        for (int r = lrow; r < 64; r += 8) {
            float4 v = *(const float4*)(qkv + (size_t)(tq0 + r) * NQKV + cb + lcol);
            v.x *= scale; v.y *= scale; v.z *= scale; v.w *= scale;
            *(float4*)(Qs + r * 132 + lcol) = v;
        }
    }

    float m_i[4], l_i[4], O[4][8];
#pragma unroll
    for (int i = 0; i < 4; i++) {
        m_i[i] = -INFINITY;
        l_i[i] = 0.0f;
#pragma unroll
        for (int j = 0; j < 8; j++) O[i][j] = 0.0f;
    }

    for (int kt = 0; kt < SS / 64; ++kt) {
        const int tk0 = b * SS + kt * 64;
#pragma unroll
        for (int r = lrow; r < 64; r += 8) {
            *(float4*)(Ks + r * 132 + lcol) =
                *(const float4*)(qkv + (size_t)(tk0 + r) * NQKV + KOFF + g * HD + lcol);
            *(float4*)(Vs + r * 132 + lcol) =
                *(const float4*)(qkv + (size_t)(tk0 + r) * NQKV + VOFF + g * HD + lcol);
        }
        __syncthreads();

        float s[4][4];
#pragma unroll
        for (int i = 0; i < 4; i++)
#pragma unroll
            for (int j = 0; j < 4; j++) s[i][j] = 0.0f;

#pragma unroll 8
        for (int kk = 0; kk < 128; kk += 4) {
            float4 q4[4], k4[4];
#pragma unroll
            for (int i = 0; i < 4; i++)
                q4[i] = *(const float4*)(Qs + (ty * 4 + i) * 132 + kk);
#pragma unroll
            for (int j = 0; j < 4; j++)
                k4[j] = *(const float4*)(Ks + (tx * 4 + j) * 132 + kk);
#pragma unroll
            for (int i = 0; i < 4; i++)
#pragma unroll
                for (int j = 0; j < 4; j++) {
                    s[i][j] += q4[i].x * k4[j].x;
                    s[i][j] += q4[i].y * k4[j].y;
                    s[i][j] += q4[i].z * k4[j].z;
                    s[i][j] += q4[i].w * k4[j].w;
                }
        }

#pragma unroll
        for (int i = 0; i < 4; i++) {
            float rm = fmaxf(fmaxf(s[i][0], s[i][1]), fmaxf(s[i][2], s[i][3]));
#pragma unroll
            for (int mk = 8; mk >= 1; mk >>= 1)
                rm = fmaxf(rm, __shfl_xor_sync(0xffffffffu, rm, mk));
            const float mn = fmaxf(m_i[i], rm);
            const float alpha = __expf(m_i[i] - mn);
            float rs = 0.0f;
#pragma unroll
            for (int j = 0; j < 4; j++) {
                s[i][j] = __expf(s[i][j] - mn);
                rs += s[i][j];
            }
#pragma unroll
            for (int mk = 8; mk >= 1; mk >>= 1)
                rs += __shfl_xor_sync(0xffffffffu, rs, mk);
            l_i[i] = l_i[i] * alpha + rs;
            m_i[i] = mn;
#pragma unroll
            for (int j = 0; j < 8; j++) O[i][j] *= alpha;
            *(float4*)(Ps + (ty * 4 + i) * 68 + tx * 4) =
                make_float4(s[i][0], s[i][1], s[i][2], s[i][3]);
        }
        __syncthreads();

#pragma unroll 8
        for (int k = 0; k < 64; ++k) {
            float p0 = Ps[(ty * 4 + 0) * 68 + k];
            float p1 = Ps[(ty * 4 + 1) * 68 + k];
            float p2 = Ps[(ty * 4 + 2) * 68 + k];
            float p3 = Ps[(ty * 4 + 3) * 68 + k];
            float4 va = *(const float4*)(Vs + k * 132 + tx * 4);
            float4 vb = *(const float4*)(Vs + k * 132 + 64 + tx * 4);
            O[0][0] += p0 * va.x; O[0][1] += p0 * va.y; O[0][2] += p0 * va.z; O[0][3] += p0 * va.w;
            O[0][4] += p0 * vb.x; O[0][5] += p0 * vb.y; O[0][6] += p0 * vb.z; O[0][7] += p0 * vb.w;
            O[1][0] += p1 * va.x; O[1][1] += p1 * va.y; O[1][2] += p1 * va.z; O[1][3] += p1 * va.w;
            O[1][4] += p1 * vb.x; O[1][5] += p1 * vb.y; O[1][6] += p1 * vb.z; O[1][7] += p1 * vb.w;
            O[2][0] += p2 * va.x; O[2][1] += p2 * va.y; O[2][2] += p2 * va.z; O[2][3] += p2 * va.w;
            O[2][4] += p2 * vb.x; O[2][5] += p2 * vb.y; O[2][6] += p2 * vb.z; O[2][7] += p2 * vb.w;
            O[3][0] += p3 * va.x; O[3][1] += p3 * va.y; O[3][2] += p3 * va.z; O[3][3] += p3 * va.w;
            O[3][4] += p3 * vb.x; O[3][5] += p3 * vb.y; O[3][6] += p3 * vb.z; O[3][7] += p3 * vb.w;
        }
        __syncthreads();
    }

#pragma unroll
    for (int i = 0; i < 4; i++) {
        const float inv = 1.0f / l_i[i];
        const int row = tq0 + ty * 4 + i;
        float* dst = attn_out + (size_t)row * HH + h * HD;
        float4 oa = make_float4(O[i][0] * inv, O[i][1] * inv, O[i][2] * inv, O[i][3] * inv);
        float4 ob = make_float4(O[i][4] * inv, O[i][5] * inv, O[i][6] * inv, O[i][7] * inv);
        *(float4*)(dst + tx * 4)      = oa;
        *(float4*)(dst + 64 + tx * 4) = ob;
    }
}

// ---------------------------------------------------------------------------
// Launch
// ---------------------------------------------------------------------------
extern "C" void kernel_launch(void* const* d_in, const int* in_sizes, int n_in,
                              void* d_out, int out_size)
{
    (void)in_sizes; (void)n_in; (void)out_size;
    const float* hs    = (const float*)d_in[0];
    const float* cosp  = (const float*)d_in[1];
    const float* sinp  = (const float*)d_in[2];
    const float* w_qkv = (const float*)d_in[3];
    const float* b_qkv = (const float*)d_in[4];
    const float* w_o   = (const float*)d_in[5];
    const float* b_o   = (const float*)d_in[6];
    float* out = (float*)d_out;

    float *qkv, *attn;
    cudaGetSymbolAddress((void**)&qkv, g_qkv);
    cudaGetSymbolAddress((void**)&attn, g_attn);

    // 1) QKV projection + bias (tf32 tensor cores)
    gemm_tf32_kernel<<<dim3(NQKV / 128, MTOK / 128), 256>>>(
        hs, w_qkv, b_qkv, qkv, MTOK, NQKV, HH);

    // 2) RoPE on q and k heads (in-place)
    {
        const int total = MTOK * (NHH + NKV) * 64;
        rope_kernel<<<(total + 255) / 256, 256>>>(qkv, cosp, sinp);
    }

    // 3) Flash attention
    cudaFuncSetAttribute((const void*)attn_kernel,
                         cudaFuncAttributeMaxDynamicSharedMemorySize,
                         ATTN_SMEM_BYTES);
    attn_kernel<<<dim3(SS / 64, NHH, BB), 256, ATTN_SMEM_BYTES>>>(qkv, attn);

    // 4) Output projection + bias -> d_out (tf32 tensor cores)
    gemm_tf32_kernel<<<dim3(HH / 128, MTOK / 128), 256>>>(
        attn, w_o, b_o, out, MTOK, HH, HH);
}

// round 5
// speedup vs baseline: 2.7234x; 1.9688x over previous
#include <cuda_runtime.h>
#include <math.h>
#include <stdint.h>

// Problem constants
#define BB   4
#define SS   2048
#define HH   2048
#define NHH  16
#define NKV  4
#define HD   128
#define MTOK (BB*SS)          // 8192 tokens
#define NQKV 3072             // (16 + 2*4) * 128
#define KOFF 2048
#define VOFF 2560

// Scratch (allocation rules forbid cudaMalloc)
__device__ float g_qkv[(size_t)MTOK * NQKV];   // ~100.7 MB
__device__ float g_attn[(size_t)MTOK * HH];    // 64 MB

// ---------------------------------------------------------------------------
// Helpers
// ---------------------------------------------------------------------------
__device__ __forceinline__ uint32_t f2tf32(float x) {
    uint32_t y;
    asm("cvt.rna.tf32.f32 %0, %1;" : "=r"(y) : "f"(x));
    return y;
}
__device__ __forceinline__ void split_tf32(float x, uint32_t& hi, uint32_t& lo) {
    hi = f2tf32(x);
    lo = f2tf32(x - __uint_as_float(hi));
}
__device__ __forceinline__ uint4 tf32x4(float4 v) {
    return make_uint4(f2tf32(v.x), f2tf32(v.y), f2tf32(v.z), f2tf32(v.w));
}
__device__ __forceinline__ uint32_t smem_u32(const void* p) {
    return (uint32_t)__cvta_generic_to_shared(p);
}
__device__ __forceinline__ void ldmatrix_x4(uint32_t* d, uint32_t addr) {
    asm volatile("ldmatrix.sync.aligned.m8n8.x4.shared.b16 {%0,%1,%2,%3}, [%4];"
                 : "=r"(d[0]), "=r"(d[1]), "=r"(d[2]), "=r"(d[3])
                 : "r"(addr));
}
__device__ __forceinline__ void mma_tf32(float* c, const uint32_t* a, const uint32_t* b) {
    asm volatile(
        "mma.sync.aligned.m16n8k8.row.col.f32.tf32.tf32.f32 "
        "{%0,%1,%2,%3}, {%4,%5,%6,%7}, {%8,%9}, {%0,%1,%2,%3};"
        : "+f"(c[0]), "+f"(c[1]), "+f"(c[2]), "+f"(c[3])
        : "r"(a[0]), "r"(a[1]), "r"(a[2]), "r"(a[3]), "r"(b[0]), "r"(b[1]));
}

// ---------------------------------------------------------------------------
// 3xTF32 tensor-core GEMM (fp32-class accuracy):
// C = A*B + bias.  a = ah+al, b = bh+bl; acc += ah*bh + ah*bl + al*bh.
// CTA tile 128x128x32, 256 threads = 8 warps (4m x 2n), warp tile 32x64.
// Dynamic smem: Ah/Al [m][k] and Bh/Bl [n][k] (B transposed), XOR swizzle.
// ---------------------------------------------------------------------------
#define GEMM_SMEM_BYTES (4 * 128 * 32 * 4)   // 64 KB

__global__ __launch_bounds__(256)
void gemm_tf32x3_kernel(const float* __restrict__ A,
                        const float* __restrict__ Bw,
                        const float* __restrict__ bias,
                        float* __restrict__ C,
                        int M, int N, int K)
{
    extern __shared__ uint32_t gsm[];
    uint32_t* Ah = gsm;
    uint32_t* Al = gsm + 128 * 32;
    uint32_t* Bh = gsm + 2 * 128 * 32;
    uint32_t* Bl = gsm + 3 * 128 * 32;

    const int tid  = threadIdx.x;
    const int lane = tid & 31;
    const int warp = tid >> 5;
    const int wm   = (warp >> 1) * 32;
    const int wn   = (warp & 1) * 64;
    const int m0   = blockIdx.y * 128;
    const int n0   = blockIdx.x * 128;

    const int q = lane >> 3;
    const int r = lane & 7;

    const uint32_t sAh = smem_u32(Ah), sAl = smem_u32(Al);
    const uint32_t sBh = smem_u32(Bh), sBl = smem_u32(Bl);

    const int rowA0 = wm + 8 * (q & 1) + r;
    const int rowB0 = wn + 8 * (q >> 1) + r;

    float acc[2][8][4];
#pragma unroll
    for (int i = 0; i < 2; i++)
#pragma unroll
        for (int j = 0; j < 8; j++)
#pragma unroll
            for (int v = 0; v < 4; v++) acc[i][j][v] = 0.0f;

    const int nk = K >> 5;
    float4 pa[4];
    float  pb[4][4];

    // prologue
#pragma unroll
    for (int it = 0; it < 4; ++it) {
        const int idx = tid + 256 * it;
        const int am = idx >> 3, ak4 = idx & 7;
        pa[it] = *(const float4*)(A + (size_t)(m0 + am) * K + 4 * ak4);
        const int bn = idx & 127, bk4 = idx >> 7;
#pragma unroll
        for (int i = 0; i < 4; i++)
            pb[it][i] = Bw[(size_t)(4 * bk4 + i) * N + n0 + bn];
    }
#pragma unroll
    for (int it = 0; it < 4; ++it) {
        const int idx = tid + 256 * it;
        const int am = idx >> 3, ak4 = idx & 7;
        const int aof = am * 32 + 4 * (ak4 ^ (am & 7));
        uint4 hA, lA;
        split_tf32(pa[it].x, hA.x, lA.x); split_tf32(pa[it].y, hA.y, lA.y);
        split_tf32(pa[it].z, hA.z, lA.z); split_tf32(pa[it].w, hA.w, lA.w);
        *(uint4*)&Ah[aof] = hA; *(uint4*)&Al[aof] = lA;
        const int bn = idx & 127, bk4 = idx >> 7;
        const int bof = bn * 32 + 4 * (bk4 ^ (bn & 7));
        uint4 hB, lB;
        split_tf32(pb[it][0], hB.x, lB.x); split_tf32(pb[it][1], hB.y, lB.y);
        split_tf32(pb[it][2], hB.z, lB.z); split_tf32(pb[it][3], hB.w, lB.w);
        *(uint4*)&Bh[bof] = hB; *(uint4*)&Bl[bof] = lB;
    }
    __syncthreads();

    for (int t = 0; t < nk; ++t) {
        if (t + 1 < nk) {
            const int k0 = (t + 1) << 5;
#pragma unroll
            for (int it = 0; it < 4; ++it) {
                const int idx = tid + 256 * it;
                const int am = idx >> 3, ak4 = idx & 7;
                pa[it] = *(const float4*)(A + (size_t)(m0 + am) * K + k0 + 4 * ak4);
                const int bn = idx & 127, bk4 = idx >> 7;
#pragma unroll
                for (int i = 0; i < 4; i++)
                    pb[it][i] = Bw[(size_t)(k0 + 4 * bk4 + i) * N + n0 + bn];
            }
        }

#pragma unroll
        for (int s = 0; s < 4; ++s) {
            uint32_t ah[2][4], al[2][4];
            const int ka = (2 * s + (q >> 1)) ^ r;
#pragma unroll
            for (int mi = 0; mi < 2; ++mi) {
                const uint32_t off = (uint32_t)(((rowA0 + 16 * mi) * 32 + 4 * ka) << 2);
                ldmatrix_x4(ah[mi], sAh + off);
                ldmatrix_x4(al[mi], sAl + off);
            }
            uint32_t bh[8][2], bl[8][2];
            const int kb = (2 * s + (q & 1)) ^ r;
#pragma unroll
            for (int jp = 0; jp < 4; ++jp) {
                const uint32_t off = (uint32_t)(((rowB0 + 16 * jp) * 32 + 4 * kb) << 2);
                uint32_t th[4], tl[4];
                ldmatrix_x4(th, sBh + off);
                ldmatrix_x4(tl, sBl + off);
                bh[2 * jp][0] = th[0]; bh[2 * jp][1] = th[1];
                bh[2 * jp + 1][0] = th[2]; bh[2 * jp + 1][1] = th[3];
                bl[2 * jp][0] = tl[0]; bl[2 * jp][1] = tl[1];
                bl[2 * jp + 1][0] = tl[2]; bl[2 * jp + 1][1] = tl[3];
            }
#pragma unroll
            for (int mi = 0; mi < 2; ++mi)
#pragma unroll
                for (int nj = 0; nj < 8; ++nj) {
                    mma_tf32(acc[mi][nj], ah[mi], bh[nj]);
                    mma_tf32(acc[mi][nj], ah[mi], bl[nj]);
                    mma_tf32(acc[mi][nj], al[mi], bh[nj]);
                }
        }
        __syncthreads();

        if (t + 1 < nk) {
#pragma unroll
            for (int it = 0; it < 4; ++it) {
                const int idx = tid + 256 * it;
                const int am = idx >> 3, ak4 = idx & 7;
                const int aof = am * 32 + 4 * (ak4 ^ (am & 7));
                uint4 hA, lA;
                split_tf32(pa[it].x, hA.x, lA.x); split_tf32(pa[it].y, hA.y, lA.y);
                split_tf32(pa[it].z, hA.z, lA.z); split_tf32(pa[it].w, hA.w, lA.w);
                *(uint4*)&Ah[aof] = hA; *(uint4*)&Al[aof] = lA;
                const int bn = idx & 127, bk4 = idx >> 7;
                const int bof = bn * 32 + 4 * (bk4 ^ (bn & 7));
                uint4 hB, lB;
                split_tf32(pb[it][0], hB.x, lB.x); split_tf32(pb[it][1], hB.y, lB.y);
                split_tf32(pb[it][2], hB.z, lB.z); split_tf32(pb[it][3], hB.w, lB.w);
                *(uint4*)&Bh[bof] = hB; *(uint4*)&Bl[bof] = lB;
            }
            __syncthreads();
        }
    }

    // epilogue: acc + bias -> C
    const int gg  = lane >> 2;
    const int tig = lane & 3;
#pragma unroll
    for (int mi = 0; mi < 2; ++mi) {
#pragma unroll
        for (int nj = 0; nj < 8; ++nj) {
            const int row = m0 + wm + 16 * mi + gg;
            const int col = n0 + wn + 8 * nj + 2 * tig;
            const float b0v = __ldg(bias + col);
            const float b1v = __ldg(bias + col + 1);
            float2 v0 = make_float2(acc[mi][nj][0] + b0v, acc[mi][nj][1] + b1v);
            float2 v1 = make_float2(acc[mi][nj][2] + b0v, acc[mi][nj][3] + b1v);
            *(float2*)(C + (size_t)row * N + col)       = v0;
            *(float2*)(C + (size_t)(row + 8) * N + col) = v1;
        }
    }
}

// ---------------------------------------------------------------------------
// RoPE (full rotation, ROT == HD == 128), in-place on Q and K heads.
// ---------------------------------------------------------------------------
__global__ __launch_bounds__(256)
void rope_kernel(float* __restrict__ qkv,
                 const float* __restrict__ cosp,
                 const float* __restrict__ sinp)
{
    const int total = MTOK * (NHH + NKV) * 64;
    int idx = blockIdx.x * blockDim.x + threadIdx.x;
    if (idx >= total) return;
    const int t    = idx / ((NHH + NKV) * 64);
    const int rem  = idx - t * ((NHH + NKV) * 64);
    const int head = rem >> 6;
    const int j    = rem & 63;
    const int base = (head < NHH) ? head * HD : KOFF + (head - NHH) * HD;

    float* p = qkv + (size_t)t * NQKV + base;
    const float x1 = p[j];
    const float x2 = p[j + 64];
    const float* cp = cosp + (size_t)t * 128;
    const float* sp = sinp + (size_t)t * 128;
    p[j]      = x1 * cp[j]      - x2 * sp[j];
    p[j + 64] = x2 * cp[j + 64] + x1 * sp[j + 64];
}

// ---------------------------------------------------------------------------
// Tensor-core flash attention (tf32, non-causal, GQA 16q/4kv, HD=128).
// CTA: 128 q-rows x one head. 8 warps x 16 q-rows. KV tiles of 64.
// Smem (u32): Ks[64][128] swizzled, Vs[64][136] padded, Ps[128][64] swizzled.
// Q staged in smem (overlaps Ks/Vs), fragments kept in registers.
// ---------------------------------------------------------------------------
#define AT_VS   (64 * 128)             // 8192
#define AT_PS   (AT_VS + 64 * 136)     // 16896
#define AT_U32  (AT_PS + 128 * 64)     // 25088
#define AT_BYTES (AT_U32 * 4)          // 100352

__global__ __launch_bounds__(256)
void attn_tc_kernel(const float* __restrict__ qkv, float* __restrict__ attn_out)
{
    extern __shared__ uint32_t sm[];
    uint32_t* Ks  = sm;
    uint32_t* Vs  = sm + AT_VS;
    uint32_t* Ps  = sm + AT_PS;
    uint32_t* Qst = sm;                 // prologue only (overlaps Ks/Vs)

    const int tid  = threadIdx.x;
    const int lane = tid & 31;
    const int warp = tid >> 5;
    const int h    = blockIdx.y;
    const int b    = blockIdx.z;
    const int g    = h >> 2;            // kv head
    const int tq0  = b * SS + blockIdx.x * 128;
    const int wq0  = warp * 16;
    const int qq   = lane >> 3;
    const int r    = lane & 7;
    const int gg   = lane >> 2;
    const int t4   = lane & 3;
    const float scale = 0.08838834764831845f;

    const uint32_t sQ = smem_u32(Qst);
    const uint32_t sK = smem_u32(Ks);
    const uint32_t sP = smem_u32(Ps);

    // ---- stage Q (scaled, tf32, swizzled) ----
#pragma unroll
    for (int i = 0; i < 16; i++) {
        const int idx = tid + 256 * i;
        const int row = idx >> 5, c4 = idx & 31;
        float4 v = *(const float4*)(qkv + (size_t)(tq0 + row) * NQKV + h * HD + 4 * c4);
        v.x *= scale; v.y *= scale; v.z *= scale; v.w *= scale;
        *(uint4*)&Qst[row * 128 + 4 * (c4 ^ (row & 7))] = tf32x4(v);
    }
    __syncthreads();

    // ---- Q fragments into registers ----
    uint32_t qf[16][4];
    {
        const int rowA = wq0 + 8 * (qq & 1) + r;
#pragma unroll
        for (int s = 0; s < 16; s++) {
            const int k4 = (2 * s + (qq >> 1)) ^ r;
            ldmatrix_x4(qf[s], sQ + (uint32_t)((rowA * 128 + 4 * k4) << 2));
        }
    }
    __syncthreads();   // Q staging region now free for K/V

    float O[16][4];
#pragma unroll
    for (int i = 0; i < 16; i++)
#pragma unroll
        for (int j = 0; j < 4; j++) O[i][j] = 0.0f;
    float m0 = -INFINITY, m1 = -INFINITY, l0 = 0.0f, l1 = 0.0f;

    const int rowB = 8 * (qq >> 1) + r;             // K-fragment base row
    const int rowP = wq0 + 8 * (qq & 1) + r;        // P-fragment base row

    for (int kt = 0; kt < SS / 64; ++kt) {
        const int tk0 = b * SS + kt * 64;
        // load K (swizzled) and V (padded row-major), tf32
#pragma unroll
        for (int i = 0; i < 8; i++) {
            const int idx = tid + 256 * i;
            const int row = idx >> 5, c4 = idx & 31;
            const float* srck = qkv + (size_t)(tk0 + row) * NQKV + KOFF + g * HD + 4 * c4;
            const float* srcv = qkv + (size_t)(tk0 + row) * NQKV + VOFF + g * HD + 4 * c4;
            *(uint4*)&Ks[row * 128 + 4 * (c4 ^ (row & 7))] = tf32x4(*(const float4*)srck);
            *(uint4*)&Vs[row * 136 + 4 * c4]               = tf32x4(*(const float4*)srcv);
        }
        __syncthreads();

        // ---- S = Q * K^T  (16 x 64 per warp) ----
        float sacc[8][4];
#pragma unroll
        for (int nj = 0; nj < 8; nj++)
#pragma unroll
            for (int v = 0; v < 4; v++) sacc[nj][v] = 0.0f;

#pragma unroll
        for (int s = 0; s < 16; s++) {
            uint32_t bf[8][2];
            const int k4 = (2 * s + (qq & 1)) ^ r;
#pragma unroll
            for (int jp = 0; jp < 4; jp++) {
                uint32_t tmp[4];
                ldmatrix_x4(tmp, sK + (uint32_t)(((rowB + 16 * jp) * 128 + 4 * k4) << 2));
                bf[2 * jp][0] = tmp[0]; bf[2 * jp][1] = tmp[1];
                bf[2 * jp + 1][0] = tmp[2]; bf[2 * jp + 1][1] = tmp[3];
            }
#pragma unroll
            for (int nj = 0; nj < 8; nj++)
                mma_tf32(sacc[nj], qf[s], bf[nj]);
        }

        // ---- online softmax (rows gg and gg+8 of the warp tile) ----
        float rm0 = -INFINITY, rm1 = -INFINITY;
#pragma unroll
        for (int nj = 0; nj < 8; nj++) {
            rm0 = fmaxf(rm0, fmaxf(sacc[nj][0], sacc[nj][1]));
            rm1 = fmaxf(rm1, fmaxf(sacc[nj][2], sacc[nj][3]));
        }
        rm0 = fmaxf(rm0, __shfl_xor_sync(0xffffffffu, rm0, 1));
        rm0 = fmaxf(rm0, __shfl_xor_sync(0xffffffffu, rm0, 2));
        rm1 = fmaxf(rm1, __shfl_xor_sync(0xffffffffu, rm1, 1));
        rm1 = fmaxf(rm1, __shfl_xor_sync(0xffffffffu, rm1, 2));

        const float mn0 = fmaxf(m0, rm0), mn1 = fmaxf(m1, rm1);
        const float a0 = __expf(m0 - mn0), a1 = __expf(m1 - mn1);
        float rs0 = 0.0f, rs1 = 0.0f;

        const int prow0 = wq0 + gg;
#pragma unroll
        for (int nj = 0; nj < 8; nj++) {
            const float p0 = __expf(sacc[nj][0] - mn0);
            const float p1 = __expf(sacc[nj][1] - mn0);
            const float p2 = __expf(sacc[nj][2] - mn1);
            const float p3 = __expf(sacc[nj][3] - mn1);
            rs0 += p0 + p1; rs1 += p2 + p3;
            const int c4s = (2 * nj + (t4 >> 1)) ^ gg;     // swizzled col granule
            const int sub = 2 * (t4 & 1);
            *(uint2*)&Ps[prow0 * 64 + 4 * c4s + sub]       = make_uint2(f2tf32(p0), f2tf32(p1));
            *(uint2*)&Ps[(prow0 + 8) * 64 + 4 * c4s + sub] = make_uint2(f2tf32(p2), f2tf32(p3));
        }
        rs0 += __shfl_xor_sync(0xffffffffu, rs0, 1);
        rs0 += __shfl_xor_sync(0xffffffffu, rs0, 2);
        rs1 += __shfl_xor_sync(0xffffffffu, rs1, 1);
        rs1 += __shfl_xor_sync(0xffffffffu, rs1, 2);
        l0 = l0 * a0 + rs0; m0 = mn0;
        l1 = l1 * a1 + rs1; m1 = mn1;
#pragma unroll
        for (int nt = 0; nt < 16; nt++) {
            O[nt][0] *= a0; O[nt][1] *= a0;
            O[nt][2] *= a1; O[nt][3] *= a1;
        }
        __syncwarp();

        // ---- O += P * V  (16 x 128 per warp) ----
#pragma unroll
        for (int s2 = 0; s2 < 8; s2++) {
            uint32_t pf[4];
            const int k4 = (2 * s2 + (qq >> 1)) ^ r;
            ldmatrix_x4(pf, sP + (uint32_t)((rowP * 64 + 4 * k4) << 2));
            const uint32_t* v0 = &Vs[(8 * s2 + t4) * 136 + gg];
            const uint32_t* v1 = &Vs[(8 * s2 + t4 + 4) * 136 + gg];
#pragma unroll
            for (int nd = 0; nd < 16; nd++) {
                uint32_t bb[2] = { v0[8 * nd], v1[8 * nd] };
                mma_tf32(O[nd], pf, bb);
            }
        }
        __syncthreads();
    }

    // ---- normalize + write ----
    const float inv0 = 1.0f / l0, inv1 = 1.0f / l1;
    const int row0 = tq0 + wq0 + gg;
    float* d0 = attn_out + (size_t)row0 * HH + h * HD;
    float* d1 = attn_out + (size_t)(row0 + 8) * HH + h * HD;
#pragma unroll
    for (int nd = 0; nd < 16; nd++) {
        const int col = 8 * nd + 2 * t4;
        *(float2*)(d0 + col) = make_float2(O[nd][0] * inv0, O[nd][1] * inv0);
        *(float2*)(d1 + col) = make_float2(O[nd][2] * inv1, O[nd][3] * inv1);
    }
}

// ---------------------------------------------------------------------------
// Launch
// ---------------------------------------------------------------------------
extern "C" void kernel_launch(void* const* d_in, const int* in_sizes, int n_in,
                              void* d_out, int out_size)
{
    (void)in_sizes; (void)n_in; (void)out_size;
    const float* hs    = (const float*)d_in[0];
    const float* cosp  = (const float*)d_in[1];
    const float* sinp  = (const float*)d_in[2];
    const float* w_qkv = (const float*)d_in[3];
    const float* b_qkv = (const float*)d_in[4];
    const float* w_o   = (const float*)d_in[5];
    const float* b_o   = (const float*)d_in[6];
    float* out = (float*)d_out;

    float *qkv, *attn;
    cudaGetSymbolAddress((void**)&qkv, g_qkv);
    cudaGetSymbolAddress((void**)&attn, g_attn);

    cudaFuncSetAttribute((const void*)gemm_tf32x3_kernel,
                         cudaFuncAttributeMaxDynamicSharedMemorySize,
                         GEMM_SMEM_BYTES);
    cudaFuncSetAttribute((const void*)attn_tc_kernel,
                         cudaFuncAttributeMaxDynamicSharedMemorySize,
                         AT_BYTES);

    // 1) QKV projection + bias (3xTF32 — fp32-class accuracy)
    gemm_tf32x3_kernel<<<dim3(NQKV / 128, MTOK / 128), 256, GEMM_SMEM_BYTES>>>(
        hs, w_qkv, b_qkv, qkv, MTOK, NQKV, HH);

    // 2) RoPE on q and k heads (in-place)
    {
        const int total = MTOK * (NHH + NKV) * 64;
        rope_kernel<<<(total + 255) / 256, 256>>>(qkv, cosp, sinp);
    }

    // 3) Tensor-core flash attention (tf32)
    attn_tc_kernel<<<dim3(SS / 128, NHH, BB), 256, AT_BYTES>>>(qkv, attn);

    // 4) Output projection + bias -> d_out (3xTF32)
    gemm_tf32x3_kernel<<<dim3(HH / 128, MTOK / 128), 256, GEMM_SMEM_BYTES>>>(
        attn, w_o, b_o, out, MTOK, HH, HH);
}